// round 15
// baseline (speedup 1.0000x reference)
#include <cuda_runtime.h>

#define N_NODES 50000
#define N_EDGES 600000
#define DIM     128
#define DOUT2   96
#define NREL    4

// ---------------------------------------------------------------------------
// Static device scratch (no allocation allowed)
// ---------------------------------------------------------------------------
__device__ float g_agg[(size_t)NREL * N_NODES * DIM];   // per-relation aggregates
__device__ float g_deg[(size_t)NREL * N_NODES];         // per-relation in-degree
__device__ float g_h[(size_t)N_NODES * DIM];            // hidden layer (post-ReLU)
__device__ int   g_is64;                                // 1 if indices are int64

// ---------------------------------------------------------------------------
// Detect whether edge_index buffer is int64 or int32 (JAX may demote).
// int32 data read as int64 gives values >= 2^32 (src[2i+1] != 0 a.s.).
// Deterministic given fixed inputs -> graph-safe.
// ---------------------------------------------------------------------------
__global__ void detect_kernel(const void* ei) {
    const long long* p = (const long long*)ei;
    int ok = 1;
    for (int i = 0; i < 64; i++) {
        long long v = p[i];
        if (v < 0 || v >= N_NODES) { ok = 0; break; }
    }
    g_is64 = ok;
}

__device__ __forceinline__ int load_idx(const void* p, size_t i, int is64) {
    if (is64) return (int)((const long long*)p)[i];
    return ((const int*)p)[i];
}

// ---------------------------------------------------------------------------
// Zero agg (and optionally deg)
// ---------------------------------------------------------------------------
__global__ void zero_kernel(int zero_deg) {
    size_t stride = (size_t)gridDim.x * blockDim.x;
    size_t tid = (size_t)blockIdx.x * blockDim.x + threadIdx.x;
    float4 z = make_float4(0.f, 0.f, 0.f, 0.f);
    float4* p = (float4*)g_agg;
    size_t n4 = (size_t)NREL * N_NODES * (DIM / 4);
    for (size_t i = tid; i < n4; i += stride) p[i] = z;
    if (zero_deg) {
        size_t nd = (size_t)NREL * N_NODES;
        for (size_t i = tid; i < nd; i += stride) g_deg[i] = 0.f;
    }
}

// ---------------------------------------------------------------------------
// Degree count: one thread per edge
// ---------------------------------------------------------------------------
__global__ void deg_kernel(const void* ei, const void* et) {
    int e = blockIdx.x * blockDim.x + threadIdx.x;
    if (e >= N_EDGES) return;
    int is64 = g_is64;
    int dst = load_idx(ei, (size_t)N_EDGES + e, is64);
    int r   = load_idx(et, e, is64);
    atomicAdd(&g_deg[(size_t)r * N_NODES + dst], 1.0f);
}

// ---------------------------------------------------------------------------
// Edge scatter: one warp per edge. Each lane moves one float4 (16B) of the
// 512B source row via vector atomicAdd (sm_90+ float4 red).
// ---------------------------------------------------------------------------
__global__ __launch_bounds__(256) void scatter_kernel(const float* __restrict__ X,
                                                      const void* ei, const void* et) {
    int idx  = blockIdx.x * blockDim.x + threadIdx.x;
    int e    = idx >> 5;
    int lane = idx & 31;
    if (e >= N_EDGES) return;
    int is64 = g_is64;
    int src = load_idx(ei, e, is64);
    int dst = load_idx(ei, (size_t)N_EDGES + e, is64);
    int r   = load_idx(et, e, is64);
    float4 v = ((const float4*)X)[(size_t)src * (DIM / 4) + lane];
    float4* d = (float4*)(g_agg + ((size_t)r * N_NODES + dst) * DIM + lane * 4);
    atomicAdd(d, v);   // float4 global atomic add (sm_90+)
}

// ---------------------------------------------------------------------------
// Fused RGCN layer GEMM.
//   out[m, :] = bias + X[m] @ Wroot + sum_r (agg[r][m]/max(deg,1)) @ Wrel[r]
// Tile: 128 nodes x DOUT per CTA, 256 threads, register tile 8 x (DOUT/16).
// Dynamic smem: sA[128][132] | sW[128][DOUT] | sInv[128]
// ---------------------------------------------------------------------------
template<int DOUT, int RELU>
__global__ __launch_bounds__(256)
void rgcn_layer_kernel(const float* __restrict__ X,
                       const float* __restrict__ Wroot,   // [DIM, DOUT]
                       const float* __restrict__ Wrel,    // [NREL, DIM, DOUT]
                       const float* __restrict__ bias,    // [DOUT]
                       float* __restrict__ out)           // [N, DOUT]
{
    constexpr int RN = DOUT / 16;   // cols per thread (8 or 6)
    constexpr int AP = 132;         // padded A row pitch (floats)

    extern __shared__ float smem[];
    float* sA   = smem;                    // 128 * 132
    float* sW   = sA + 128 * AP;           // 128 * DOUT
    float* sInv = sW + 128 * DOUT;         // 128

    const int tid = threadIdx.x;
    const int tx  = tid & 15;              // n-group
    const int ty  = tid >> 4;              // m-group (0..15)
    const int m0  = blockIdx.x * 128;

    float acc[8][RN];
#pragma unroll
    for (int j = 0; j < 8; j++)
#pragma unroll
        for (int i = 0; i < RN; i++) acc[j][i] = 0.f;

    for (int s = 0; s < 5; s++) {
        __syncthreads();  // previous compute done before smem overwrite
        if (s > 0 && tid < 128) {
            int row = m0 + tid;
            float d = (row < N_NODES) ? g_deg[(size_t)(s - 1) * N_NODES + row] : 1.f;
            sInv[tid] = 1.0f / fmaxf(d, 1.0f);
        }
        __syncthreads();

        // --- load A tile (128 x 128 floats) ---
        const float* Asrc = (s == 0) ? X : (g_agg + (size_t)(s - 1) * N_NODES * DIM);
#pragma unroll
        for (int t = 0; t < 16; t++) {
            int idx = tid + t * 256;          // 4096 float4 slots
            int row = idx >> 5;               // 0..127
            int c4  = idx & 31;
            float4 v = make_float4(0.f, 0.f, 0.f, 0.f);
            int grow = m0 + row;
            if (grow < N_NODES)
                v = ((const float4*)Asrc)[(size_t)grow * (DIM / 4) + c4];
            if (s > 0) {
                float iv = sInv[row];
                v.x *= iv; v.y *= iv; v.z *= iv; v.w *= iv;
            }
            *(float4*)&sA[row * AP + c4 * 4] = v;
        }

        // --- load W tile (128 x DOUT floats, contiguous) ---
        const float* Wsrc = (s == 0) ? Wroot : (Wrel + (size_t)(s - 1) * DIM * DOUT);
        constexpr int WL = (DIM * DOUT / 4) / 256;
#pragma unroll
        for (int t = 0; t < WL; t++) {
            int idx = tid + t * 256;
            ((float4*)sW)[idx] = ((const float4*)Wsrc)[idx];
        }
        __syncthreads();

        // --- FFMA mainloop over K=128 ---
#pragma unroll 4
        for (int k = 0; k < DIM; k++) {
            float w[RN];
#pragma unroll
            for (int i = 0; i < RN; i++) w[i] = sW[k * DOUT + tx + 16 * i];
#pragma unroll
            for (int j = 0; j < 8; j++) {
                float a = sA[(ty + 16 * j) * AP + k];
#pragma unroll
                for (int i = 0; i < RN; i++) acc[j][i] = fmaf(a, w[i], acc[j][i]);
            }
        }
    }

    // --- epilogue: bias (+ ReLU), store ---
#pragma unroll
    for (int j = 0; j < 8; j++) {
        int grow = m0 + ty + 16 * j;
        if (grow >= N_NODES) continue;
#pragma unroll
        for (int i = 0; i < RN; i++) {
            int n = tx + 16 * i;
            float v = acc[j][i] + __ldg(&bias[n]);
            if (RELU) v = fmaxf(v, 0.f);
            out[(size_t)grow * DOUT + n] = v;
        }
    }
}

// ---------------------------------------------------------------------------
// Launch
// ---------------------------------------------------------------------------
extern "C" void kernel_launch(void* const* d_in, const int* in_sizes, int n_in,
                              void* d_out, int out_size) {
    const float* x       = (const float*)d_in[0];
    const void*  ei      = d_in[1];           // [2, E] int64 or int32
    const void*  et      = d_in[2];           // [E]
    const float* W_root1 = (const float*)d_in[3];
    const float* W_rel1  = (const float*)d_in[4];
    const float* b1      = (const float*)d_in[5];
    const float* W_root2 = (const float*)d_in[6];
    const float* W_rel2  = (const float*)d_in[7];
    const float* b2      = (const float*)d_in[8];
    float* out = (float*)d_out;

    float* h;
    cudaGetSymbolAddress((void**)&h, g_h);

    const int smem1 = (128 * 132 + 128 * DIM   + 128) * 4;   // 133632 B
    const int smem2 = (128 * 132 + 128 * DOUT2 + 128) * 4;   // 117248 B
    cudaFuncSetAttribute(rgcn_layer_kernel<DIM, 1>,
                         cudaFuncAttributeMaxDynamicSharedMemorySize, smem1);
    cudaFuncSetAttribute(rgcn_layer_kernel<DOUT2, 0>,
                         cudaFuncAttributeMaxDynamicSharedMemorySize, smem2);

    const int ZB = 1184;                              // zero kernel blocks
    const int DB = (N_EDGES + 255) / 256;             // deg kernel blocks
    const int SB = (N_EDGES * 32) / 256;              // scatter blocks (warp/edge)
    const int GB = (N_NODES + 127) / 128;             // gemm blocks

    detect_kernel<<<1, 1>>>(ei);

    // ---- layer 1 ----
    zero_kernel<<<ZB, 256>>>(1);
    deg_kernel<<<DB, 256>>>(ei, et);
    scatter_kernel<<<SB, 256>>>(x, ei, et);
    rgcn_layer_kernel<DIM, 1><<<GB, 256, smem1>>>(x, W_root1, W_rel1, b1, h);

    // ---- layer 2 ----
    zero_kernel<<<ZB, 256>>>(0);
    scatter_kernel<<<SB, 256>>>(h, ei, et);
    rgcn_layer_kernel<DOUT2, 0><<<GB, 256, smem2>>>(h, W_root2, W_rel2, b2, out);
}

// round 16
// speedup vs baseline: 1.0994x; 1.0994x over previous
#include <cuda_runtime.h>

#define N_NODES 50000
#define N_EDGES 600000
#define DIM     128
#define DOUT2   96
#define NREL    4

// ---------------------------------------------------------------------------
// Static device scratch (no allocation allowed)
// ---------------------------------------------------------------------------
__device__ float g_agg[(size_t)NREL * N_NODES * DIM];   // per-relation aggregates
__device__ float g_deg[(size_t)NREL * N_NODES];         // degree -> reciprocal
__device__ float g_h[(size_t)N_NODES * DIM];            // hidden layer (post-ReLU)
__device__ int   g_is64;                                // 1 if indices are int64

// ---------------------------------------------------------------------------
// Detect int64 vs int32 indices (JAX may demote). Deterministic.
// ---------------------------------------------------------------------------
__global__ void detect_kernel(const void* ei) {
    const long long* p = (const long long*)ei;
    int ok = 1;
    for (int i = 0; i < 64; i++) {
        long long v = p[i];
        if (v < 0 || v >= N_NODES) { ok = 0; break; }
    }
    g_is64 = ok;
}

__device__ __forceinline__ int load_idx(const void* p, size_t i, int is64) {
    if (is64) return (int)((const long long*)p)[i];
    return ((const int*)p)[i];
}

// ---------------------------------------------------------------------------
// Zero agg (and optionally deg)
// ---------------------------------------------------------------------------
__global__ void zero_kernel(int zero_deg) {
    size_t stride = (size_t)gridDim.x * blockDim.x;
    size_t tid = (size_t)blockIdx.x * blockDim.x + threadIdx.x;
    float4 z = make_float4(0.f, 0.f, 0.f, 0.f);
    float4* p = (float4*)g_agg;
    size_t n4 = (size_t)NREL * N_NODES * (DIM / 4);
    for (size_t i = tid; i < n4; i += stride) p[i] = z;
    if (zero_deg) {
        size_t nd = (size_t)NREL * N_NODES;
        for (size_t i = tid; i < nd; i += stride) g_deg[i] = 0.f;
    }
}

// ---------------------------------------------------------------------------
// Degree count then reciprocal (edges only -> computed once, reused by layer 2)
// ---------------------------------------------------------------------------
__global__ void deg_kernel(const void* ei, const void* et) {
    int e = blockIdx.x * blockDim.x + threadIdx.x;
    if (e >= N_EDGES) return;
    int is64 = g_is64;
    int dst = load_idx(ei, (size_t)N_EDGES + e, is64);
    int r   = load_idx(et, e, is64);
    atomicAdd(&g_deg[(size_t)r * N_NODES + dst], 1.0f);
}

__global__ void rcp_kernel() {
    int i = blockIdx.x * blockDim.x + threadIdx.x;
    if (i < NREL * N_NODES) g_deg[i] = 1.0f / fmaxf(g_deg[i], 1.0f);
}

// ---------------------------------------------------------------------------
// Edge scatter: one warp per edge, pre-scaled by reciprocal degree so the
// GEMM consumes agg rows raw (sum_j x_j * inv == inv * sum_j x_j up to rounding).
// ---------------------------------------------------------------------------
__global__ __launch_bounds__(256) void scatter_kernel(const float* __restrict__ X,
                                                      const void* ei, const void* et) {
    int idx  = blockIdx.x * blockDim.x + threadIdx.x;
    int e    = idx >> 5;
    int lane = idx & 31;
    if (e >= N_EDGES) return;
    int is64 = g_is64;
    int src = load_idx(ei, e, is64);
    int dst = load_idx(ei, (size_t)N_EDGES + e, is64);
    int r   = load_idx(et, e, is64);
    float inv = g_deg[(size_t)r * N_NODES + dst];   // holds 1/max(deg,1)
    float4 v = ((const float4*)X)[(size_t)src * (DIM / 4) + lane];
    v.x *= inv; v.y *= inv; v.z *= inv; v.w *= inv;
    float4* d = (float4*)(g_agg + ((size_t)r * N_NODES + dst) * DIM + lane * 4);
    atomicAdd(d, v);   // float4 global red (sm_90+)
}

// ---------------------------------------------------------------------------
// cp.async helpers
// ---------------------------------------------------------------------------
__device__ __forceinline__ void cp16(float* dst, const float4* src, bool pred) {
    unsigned sa = (unsigned)__cvta_generic_to_shared(dst);
    int sz = pred ? 16 : 0;
    asm volatile("cp.async.cg.shared.global [%0], [%1], 16, %2;\n"
                 :: "r"(sa), "l"(src), "r"(sz));
}
__device__ __forceinline__ void cp_commit() {
    asm volatile("cp.async.commit_group;\n");
}
__device__ __forceinline__ void cp_wait_all() {
    asm volatile("cp.async.wait_group 0;\n");
}

// ---------------------------------------------------------------------------
// Fused RGCN layer GEMM with packed fma.rn.f32x2 and double-buffered A tiles.
//   out[m,:] = bias + X[m]@Wroot + sum_r agg[r][m]@Wrel[r]   (agg pre-normalized)
// Tile: 128 nodes x DOUT per CTA, 256 threads.
// Thread (tx,ty): rows ty+16j (j=0..7), column pairs 2*tx+32*i (i=0..RN/2-1).
// Dynamic smem: A0[128][132] | A1[128][132] | W[128][DOUT]
// ---------------------------------------------------------------------------
#define AP 132   // padded A row pitch in floats (132*4 = 528, 16B multiple)

template<int DOUT, int RELU>
__global__ __launch_bounds__(256)
void rgcn_layer_kernel(const float* __restrict__ X,
                       const float* __restrict__ Wroot,   // [DIM, DOUT]
                       const float* __restrict__ Wrel,    // [NREL, DIM, DOUT]
                       const float* __restrict__ bias,    // [DOUT]
                       float* __restrict__ out)           // [N, DOUT]
{
    constexpr int RN2 = DOUT / 32;          // column pairs per thread (4 or 3)
    constexpr int WCH = (DIM * DOUT / 4) / 256;  // float4 chunks of W per thread

    extern __shared__ float smem[];
    float* sA[2] = { smem, smem + 128 * AP };
    float* sW    = smem + 2 * 128 * AP;

    const int tid = threadIdx.x;
    const int tx  = tid & 15;
    const int ty  = tid >> 4;
    const int m0  = blockIdx.x * 128;

    unsigned long long acc[8][RN2] = {};

    // ---- tile issue lambdas ----
    auto issueA = [&](int s, int buf) {
        const float* src = (s == 0) ? X : (g_agg + (size_t)(s - 1) * N_NODES * DIM);
#pragma unroll
        for (int t = 0; t < 16; t++) {
            int idx = tid + t * 256;        // 4096 float4 slots
            int row = idx >> 5;
            int c4  = idx & 31;
            int grow = m0 + row;
            bool ok = grow < N_NODES;
            int srow = ok ? grow : 0;
            cp16(&sA[buf][row * AP + c4 * 4],
                 (const float4*)src + (size_t)srow * (DIM / 4) + c4, ok);
        }
        cp_commit();
    };
    auto issueW = [&](int s) {
        const float* src = (s == 0) ? Wroot : (Wrel + (size_t)(s - 1) * DIM * DOUT);
#pragma unroll
        for (int t = 0; t < WCH; t++) {
            int idx = tid + t * 256;
            cp16(&sW[idx * 4], (const float4*)src + idx, true);
        }
        cp_commit();
    };

    // ---- prologue ----
    issueA(0, 0);
    issueW(0);
    cp_wait_all();
    __syncthreads();

    for (int s = 0; s < 5; s++) {
        if (s < 4) issueA(s + 1, (s + 1) & 1);   // prefetch next A during compute

        const float* A = sA[s & 1];
#pragma unroll 4
        for (int k = 0; k < DIM; k += 2) {
            unsigned long long w0[RN2], w1[RN2];
#pragma unroll
            for (int i = 0; i < RN2; i++) {
                w0[i] = *(const unsigned long long*)&sW[k * DOUT + 2 * tx + 32 * i];
                w1[i] = *(const unsigned long long*)&sW[(k + 1) * DOUT + 2 * tx + 32 * i];
            }
#pragma unroll
            for (int j = 0; j < 8; j++) {
                float2 av = *(const float2*)&A[(ty + 16 * j) * AP + k];
                unsigned long long A0, A1;
                asm("mov.b64 %0, {%1, %1};" : "=l"(A0) : "r"(__float_as_uint(av.x)));
                asm("mov.b64 %0, {%1, %1};" : "=l"(A1) : "r"(__float_as_uint(av.y)));
#pragma unroll
                for (int i = 0; i < RN2; i++) {
                    asm("fma.rn.f32x2 %0, %1, %2, %0;" : "+l"(acc[j][i]) : "l"(A0), "l"(w0[i]));
                    asm("fma.rn.f32x2 %0, %1, %2, %0;" : "+l"(acc[j][i]) : "l"(A1), "l"(w1[i]));
                }
            }
        }
        __syncthreads();           // compute done; sW free to overwrite
        if (s < 4) {
            issueW(s + 1);
            cp_wait_all();         // A(s+1) overlapped with compute; W(s+1) short
            __syncthreads();
        }
    }

    // ---- epilogue: bias (+ ReLU), store as float2 ----
#pragma unroll
    for (int j = 0; j < 8; j++) {
        int grow = m0 + ty + 16 * j;
        if (grow >= N_NODES) continue;
#pragma unroll
        for (int i = 0; i < RN2; i++) {
            int c = 2 * tx + 32 * i;
            unsigned int lo = (unsigned int)(acc[j][i] & 0xFFFFFFFFull);
            unsigned int hi = (unsigned int)(acc[j][i] >> 32);
            float2 v = make_float2(__uint_as_float(lo) + __ldg(&bias[c]),
                                   __uint_as_float(hi) + __ldg(&bias[c + 1]));
            if (RELU) { v.x = fmaxf(v.x, 0.f); v.y = fmaxf(v.y, 0.f); }
            *(float2*)&out[(size_t)grow * DOUT + c] = v;
        }
    }
}

// ---------------------------------------------------------------------------
// Launch
// ---------------------------------------------------------------------------
extern "C" void kernel_launch(void* const* d_in, const int* in_sizes, int n_in,
                              void* d_out, int out_size) {
    const float* x       = (const float*)d_in[0];
    const void*  ei      = d_in[1];           // [2, E] int64 or int32
    const void*  et      = d_in[2];           // [E]
    const float* W_root1 = (const float*)d_in[3];
    const float* W_rel1  = (const float*)d_in[4];
    const float* b1      = (const float*)d_in[5];
    const float* W_root2 = (const float*)d_in[6];
    const float* W_rel2  = (const float*)d_in[7];
    const float* b2      = (const float*)d_in[8];
    float* out = (float*)d_out;

    float* h;
    cudaGetSymbolAddress((void**)&h, g_h);

    const int smem1 = (2 * 128 * AP + 128 * DIM)   * 4;   // 200704 B
    const int smem2 = (2 * 128 * AP + 128 * DOUT2) * 4;   // 184320 B
    cudaFuncSetAttribute(rgcn_layer_kernel<DIM, 1>,
                         cudaFuncAttributeMaxDynamicSharedMemorySize, smem1);
    cudaFuncSetAttribute(rgcn_layer_kernel<DOUT2, 0>,
                         cudaFuncAttributeMaxDynamicSharedMemorySize, smem2);

    const int ZB = 1184;                              // zero kernel blocks
    const int DB = (N_EDGES + 255) / 256;             // deg kernel blocks
    const int RB = (NREL * N_NODES + 255) / 256;      // rcp kernel blocks
    const int SB = (N_EDGES * 32) / 256;              // scatter blocks (warp/edge)
    const int GB = (N_NODES + 127) / 128;             // gemm blocks

    detect_kernel<<<1, 1>>>(ei);

    // ---- shared degree reciprocal (edges fixed across layers) ----
    zero_kernel<<<ZB, 256>>>(1);
    deg_kernel<<<DB, 256>>>(ei, et);
    rcp_kernel<<<RB, 256>>>();

    // ---- layer 1 ----
    scatter_kernel<<<SB, 256>>>(x, ei, et);
    rgcn_layer_kernel<DIM, 1><<<GB, 256, smem1>>>(x, W_root1, W_rel1, b1, h);

    // ---- layer 2 ----
    zero_kernel<<<ZB, 256>>>(0);
    scatter_kernel<<<SB, 256>>>(h, ei, et);
    rgcn_layer_kernel<DOUT2, 0><<<GB, 256, smem2>>>(h, W_root2, W_rel2, b2, out);
}